// round 9
// baseline (speedup 1.0000x reference)
#include <cuda_runtime.h>
#include <cuda_bf16.h>

#define CDIM 1024
#define TT   2048
#define BB   4
#define NH   16
#define HD   64
#define MROWS 8192          // BB*TT
#define NQKV  3072

// ---------------- scratch (__device__ globals; allocation-free rule) --------
__device__ __align__(16) __nv_bfloat16 g_Xh[(size_t)MROWS*CDIM];
__device__ __align__(16) __nv_bfloat16 g_Xl[(size_t)MROWS*CDIM];
__device__ __align__(16) __nv_bfloat16 g_WQh[(size_t)NQKV*CDIM];
__device__ __align__(16) __nv_bfloat16 g_WQl[(size_t)NQKV*CDIM];
__device__ __align__(16) __nv_bfloat16 g_WPh[(size_t)CDIM*CDIM];
__device__ __align__(16) __nv_bfloat16 g_WPl[(size_t)CDIM*CDIM];
__device__ __align__(16) __nv_bfloat16 g_Qh[(size_t)BB*NH*TT*HD];
__device__ __align__(16) __nv_bfloat16 g_Ql[(size_t)BB*NH*TT*HD];
__device__ __align__(16) __nv_bfloat16 g_Kh[(size_t)BB*NH*TT*HD];
__device__ __align__(16) __nv_bfloat16 g_Kl[(size_t)BB*NH*TT*HD];
__device__ __align__(16) __nv_bfloat16 g_Vh[(size_t)BB*NH*TT*HD];
__device__ __align__(16) __nv_bfloat16 g_Vl[(size_t)BB*NH*TT*HD];
__device__ __align__(16) __nv_bfloat16 g_Ch[(size_t)MROWS*CDIM];
__device__ __align__(16) __nv_bfloat16 g_Cl[(size_t)MROWS*CDIM];

// ---------------- helpers ---------------------------------------------------
__device__ __forceinline__ void mma16816(float* c, const unsigned* a, const unsigned* b)
{
    asm volatile(
        "mma.sync.aligned.m16n8k16.row.col.f32.bf16.bf16.f32 "
        "{%0,%1,%2,%3}, {%4,%5,%6,%7}, {%8,%9}, {%0,%1,%2,%3};\n"
        : "+f"(c[0]), "+f"(c[1]), "+f"(c[2]), "+f"(c[3])
        : "r"(a[0]), "r"(a[1]), "r"(a[2]), "r"(a[3]), "r"(b[0]), "r"(b[1]));
}

#define LDSM4(rg, addr) \
    asm volatile("ldmatrix.sync.aligned.m8n8.x4.shared.b16 {%0,%1,%2,%3}, [%4];" \
                 : "=r"((rg)[0]), "=r"((rg)[1]), "=r"((rg)[2]), "=r"((rg)[3]) : "r"(addr))
#define LDSM2T(rg, addr) \
    asm volatile("ldmatrix.sync.aligned.m8n8.x2.trans.shared.b16 {%0,%1}, [%2];" \
                 : "=r"((rg)[0]), "=r"((rg)[1]) : "r"(addr))
#define CP16(dst, src) \
    asm volatile("cp.async.cg.shared.global [%0], [%1], 16;" :: "r"(dst), "l"(src))
#define CP_COMMIT() asm volatile("cp.async.commit_group;" ::: "memory")

// pack two floats into bf16x2 hi part, return lo-residual pack via out param
__device__ __forceinline__ unsigned pack_hl(float a, float b, unsigned& lo)
{
    __nv_bfloat162 h = __floats2bfloat162_rn(a, b);
    float ra = a - __bfloat162float(h.x);
    float rb = b - __bfloat162float(h.y);
    __nv_bfloat162 l = __floats2bfloat162_rn(ra, rb);
    lo = *reinterpret_cast<unsigned*>(&l);
    return *reinterpret_cast<unsigned*>(&h);
}

// ---------------- split fp32 -> (hi, lo) bf16 -------------------------------
__global__ __launch_bounds__(256)
void split_kernel(const float* __restrict__ src, __nv_bfloat16* __restrict__ hi,
                  __nv_bfloat16* __restrict__ lo, int n4)
{
    int i = blockIdx.x * 256 + threadIdx.x;
    if (i >= n4) return;
    float4 v = ((const float4*)src)[i];
    unsigned l0, l1;
    unsigned h0 = pack_hl(v.x, v.y, l0);
    unsigned h1 = pack_hl(v.z, v.w, l1);
    ((uint2*)hi)[i] = make_uint2(h0, h1);
    ((uint2*)lo)[i] = make_uint2(l0, l1);
}

// ---------------- GEMM: C[m,n] = sum_k A[m,k]*W[n,k]  (bf16x3, mma.sync) ----
// 128x128x32 tile, 256 threads, 2 CTAs/SM, cp.async 2-stage, single barrier.
// Dynamic smem: 2 stages x {Ah,Al,Bh,Bl}[128][40] bf16 = 81920 B.
#define GSTG 20480
#define QSCALE 0.18033688f   // 0.125 * log2(e): folds softmax base-2 into Q

template<int MODE>
__device__ __forceinline__ void gemm_load_tile(
    unsigned sb, int so,
    const __nv_bfloat16* Ah, const __nv_bfloat16* Al,
    const __nv_bfloat16* Bh, const __nv_bfloat16* Bl,
    int m0, int n0, int kt, int tid)
{
    #pragma unroll
    for (int r = 0; r < 2; r++) {
        int c = tid + r * 256;          // 512 16B-chunks (128 rows x 4)
        int row = c >> 2, c4 = c & 3;
        size_t ga = (size_t)(m0 + row) * CDIM + kt + c4 * 8;
        size_t gb = (size_t)(n0 + row) * CDIM + kt + c4 * 8;
        unsigned d = sb + 2u * (so + row * 40 + c4 * 8);
        CP16(d,               Ah + ga);
        CP16(d + 2u * 5120,   Al + ga);
        CP16(d + 2u * 10240,  Bh + gb);
        CP16(d + 2u * 15360,  Bl + gb);
    }
    CP_COMMIT();
}

template<int MODE>
__global__ __launch_bounds__(256, 2)
void gemm_mma_kernel(float* __restrict__ Cout)
{
    extern __shared__ __nv_bfloat16 dsm[];
    const unsigned sb = (unsigned)__cvta_generic_to_shared(dsm);

    const __nv_bfloat16* Ah = (MODE == 0) ? g_Xh  : g_Ch;
    const __nv_bfloat16* Al = (MODE == 0) ? g_Xl  : g_Cl;
    const __nv_bfloat16* Bh = (MODE == 0) ? g_WQh : g_WPh;
    const __nv_bfloat16* Bl = (MODE == 0) ? g_WQl : g_WPl;

    const int tid  = threadIdx.x;
    const int lane = tid & 31;
    const int wrp  = tid >> 5;          // 0..7
    const int g    = lane >> 2;         // 0..7
    const int tig  = lane & 3;          // 0..3
    const int wm   = wrp >> 2;          // 0..1 (64 rows each)
    const int wn   = wrp & 3;           // 0..3 (32 cols each)
    const int m0   = blockIdx.y * 128;
    const int n0   = blockIdx.x * 128;

    // ldmatrix.x4 per-lane offsets (elements within a stage array)
    const int a_off = (wm * 64 + (lane & 15)) * 40 + 8 * ((lane >> 4) & 1);
    const int b_off = (wn * 32 + (lane & 15)) * 40 + 8 * ((lane >> 4) & 1);

    float acc[4][4][4];
    #pragma unroll
    for (int a = 0; a < 4; a++)
        #pragma unroll
        for (int b = 0; b < 4; b++)
            #pragma unroll
            for (int c = 0; c < 4; c++) acc[a][b][c] = 0.f;

    gemm_load_tile<MODE>(sb, 0, Ah, Al, Bh, Bl, m0, n0, 0, tid);

    #pragma unroll 1
    for (int t = 0; t < CDIM / 32; t++) {
        asm volatile("cp.async.wait_group 0;" ::: "memory");
        __syncthreads();
        if (t < CDIM / 32 - 1)
            gemm_load_tile<MODE>(sb, ((t + 1) & 1) * GSTG, Ah, Al, Bh, Bl,
                                 m0, n0, (t + 1) * 32, tid);
        const int so = (t & 1) * GSTG;
        #pragma unroll
        for (int kk = 0; kk < 32; kk += 16) {
            // B fragments: ldmatrix.x4 covers 2 n-tiles x both k-halves
            unsigned bfh[4][2], bfl[4][2];
            #pragma unroll
            for (int p = 0; p < 2; p++) {
                unsigned r[4], rl[4];
                unsigned baddr = sb + 2u * (so + 10240 + b_off + p * 640 + kk);
                LDSM4(r,  baddr);
                LDSM4(rl, baddr + 2u * 5120);
                bfh[2*p][0] = r[0];  bfh[2*p+1][0] = r[1];
                bfh[2*p][1] = r[2];  bfh[2*p+1][1] = r[3];
                bfl[2*p][0] = rl[0]; bfl[2*p+1][0] = rl[1];
                bfl[2*p][1] = rl[2]; bfl[2*p+1][1] = rl[3];
            }
            // A fragments loaded per-mt (keeps live regs < 128 for 2 CTAs/SM)
            #pragma unroll
            for (int mt = 0; mt < 4; mt++) {
                unsigned afh[4], afl[4];
                unsigned aaddr = sb + 2u * (so + a_off + mt * 640 + kk);
                LDSM4(afh, aaddr);
                LDSM4(afl, aaddr + 2u * 5120);
                #pragma unroll
                for (int nt = 0; nt < 4; nt++) mma16816(acc[mt][nt], afh, bfh[nt]);
                #pragma unroll
                for (int nt = 0; nt < 4; nt++) mma16816(acc[mt][nt], afh, bfl[nt]);
                #pragma unroll
                for (int nt = 0; nt < 4; nt++) mma16816(acc[mt][nt], afl, bfh[nt]);
            }
        }
    }

    // ---------------- epilogue ----------------
    #pragma unroll
    for (int mt = 0; mt < 4; mt++) {
        int row = m0 + wm * 64 + mt * 16 + g;       // row g; row+8 for c2/c3
        #pragma unroll
        for (int nt = 0; nt < 4; nt++) {
            int n = n0 + wn * 32 + nt * 8 + 2 * tig;
            float v0 = acc[mt][nt][0], v1 = acc[mt][nt][1];
            float v2 = acc[mt][nt][2], v3 = acc[mt][nt][3];
            if (MODE == 1) {
                *(float2*)(Cout + (size_t)row * CDIM + n)       = make_float2(v0, v1);
                *(float2*)(Cout + (size_t)(row + 8) * CDIM + n) = make_float2(v2, v3);
            } else {
                int part = n >> 10;                 // 0=q 1=k 2=v
                int cc   = n & (CDIM - 1);
                int h    = cc >> 6;
                int d    = cc & 63;
                int b    = row >> 11;
                int tq   = row & (TT - 1);
                if (part == 0) { v0 *= QSCALE; v1 *= QSCALE; v2 *= QSCALE; v3 *= QSCALE; }
                __nv_bfloat16* dh = (part == 0) ? g_Qh : (part == 1) ? g_Kh : g_Vh;
                __nv_bfloat16* dl = (part == 0) ? g_Ql : (part == 1) ? g_Kl : g_Vl;
                size_t base = (((size_t)(b * NH + h)) * TT + tq) * HD + d;
                unsigned lp;
                unsigned hp = pack_hl(v0, v1, lp);
                *(unsigned*)(dh + base) = hp;  *(unsigned*)(dl + base) = lp;
                hp = pack_hl(v2, v3, lp);
                *(unsigned*)(dh + base + 8 * HD) = hp;  *(unsigned*)(dl + base + 8 * HD) = lp;
            }
        }
    }
}

// ---------------- causal flash attention (bf16x3 mma) -----------------------
// grid = (16 qtiles of 128 rows, 64 bh). 256 threads (8 warps, 16 q-rows each).
// Q is pre-scaled by 0.125*log2e -> softmax uses exp2f (base-2, exactly equal).
__global__ __launch_bounds__(256)
void attn_mma_kernel()
{
    __shared__ __align__(16) __nv_bfloat16 Khs[64][72];
    __shared__ __align__(16) __nv_bfloat16 Kls[64][72];
    __shared__ __align__(16) __nv_bfloat16 Vhs[64][72];
    __shared__ __align__(16) __nv_bfloat16 Vls[64][72];

    const int tid  = threadIdx.x;
    const int lane = tid & 31;
    const int wrp  = tid >> 5;                  // 0..7
    const int g    = lane >> 2;
    const int tig  = lane & 3;
    const int qt   = (int)gridDim.x - 1 - (int)blockIdx.x;   // heavy tiles first
    const int bh   = blockIdx.y;
    const int qg0  = qt * 128 + 16 * wrp + g;
    const int qg1  = qg0 + 8;

    const size_t hb = (size_t)bh * TT * HD;

    // ldmatrix.x4 per-lane offset for K-fragments (elements, row stride 72)
    const int k_off = (lane & 15) * 72 + 8 * ((lane >> 4) & 1);
    const unsigned khs_b = (unsigned)__cvta_generic_to_shared(&Khs[0][0]);
    const unsigned kls_b = (unsigned)__cvta_generic_to_shared(&Kls[0][0]);

    // Q fragments (hi & lo) in registers, reused across all j-tiles
    unsigned qh[4][4], ql[4][4];
    {
        const __nv_bfloat16* Qhp = g_Qh + hb;
        const __nv_bfloat16* Qlp = g_Ql + hb;
        #pragma unroll
        for (int kt = 0; kt < 4; kt++) {
            size_t r0 = (size_t)qg0 * HD + 16 * kt + 2 * tig;
            size_t r1 = (size_t)qg1 * HD + 16 * kt + 2 * tig;
            qh[kt][0] = *(const unsigned*)(Qhp + r0);
            qh[kt][1] = *(const unsigned*)(Qhp + r1);
            qh[kt][2] = *(const unsigned*)(Qhp + r0 + 8);
            qh[kt][3] = *(const unsigned*)(Qhp + r1 + 8);
            ql[kt][0] = *(const unsigned*)(Qlp + r0);
            ql[kt][1] = *(const unsigned*)(Qlp + r1);
            ql[kt][2] = *(const unsigned*)(Qlp + r0 + 8);
            ql[kt][3] = *(const unsigned*)(Qlp + r1 + 8);
        }
    }

    float oacc[8][4];
    #pragma unroll
    for (int nt = 0; nt < 8; nt++)
        #pragma unroll
        for (int c = 0; c < 4; c++) oacc[nt][c] = 0.f;
    float m0r = -1e30f, m1r = -1e30f, l0r = 0.f, l1r = 0.f;

    const int ntiles = 2 * qt + 2;
    for (int jt = 0; jt < ntiles; jt++) {
        const int j0 = jt * 64;
        __syncthreads();
        // 64 rows x 64 bf16 = 512 16B-chunks per array; 256 threads x 2 reps.
        #pragma unroll
        for (int r = 0; r < 2; r++) {
            int c   = tid + r * 256;            // 0..511
            int row = c >> 3, c4 = c & 7;       // 8 chunks per 64-col row
            size_t go = hb + (size_t)(j0 + row) * HD + c4 * 8;
            *(uint4*)&Khs[row][c4 * 8] = *(const uint4*)(g_Kh + go);
            *(uint4*)&Kls[row][c4 * 8] = *(const uint4*)(g_Kl + go);
            *(uint4*)&Vhs[row][c4 * 8] = *(const uint4*)(g_Vh + go);
            *(uint4*)&Vls[row][c4 * 8] = *(const uint4*)(g_Vl + go);
        }
        __syncthreads();

        // ---- S = Q K^T (3-pass hi/lo, pass-outer per kt) ----
        float sacc[8][4];
        #pragma unroll
        for (int nt = 0; nt < 8; nt++)
            #pragma unroll
            for (int c = 0; c < 4; c++) sacc[nt][c] = 0.f;

        #pragma unroll
        for (int kt = 0; kt < 4; kt++) {
            unsigned khf[8][2], klf[8][2];
            #pragma unroll
            for (int p = 0; p < 4; p++) {
                unsigned r[4], rl[4];
                unsigned a = 2u * (k_off + p * 1152 + 16 * kt);
                LDSM4(r,  khs_b + a);
                LDSM4(rl, kls_b + a);
                khf[2*p][0] = r[0];  khf[2*p+1][0] = r[1];
                khf[2*p][1] = r[2];  khf[2*p+1][1] = r[3];
                klf[2*p][0] = rl[0]; klf[2*p+1][0] = rl[1];
                klf[2*p][1] = rl[2]; klf[2*p+1][1] = rl[3];
            }
            #pragma unroll
            for (int nt = 0; nt < 8; nt++) mma16816(sacc[nt], qh[kt], khf[nt]);
            #pragma unroll
            for (int nt = 0; nt < 8; nt++) mma16816(sacc[nt], qh[kt], klf[nt]);
            #pragma unroll
            for (int nt = 0; nt < 8; nt++) mma16816(sacc[nt], ql[kt], khf[nt]);
        }

        // ---- causal mask (only tiles that can touch the diagonal) ----
        if (j0 + 63 > qt * 128 + 16 * wrp) {
            #pragma unroll
            for (int nt = 0; nt < 8; nt++) {
                int jg = j0 + 8 * nt + 2 * tig;
                if (jg     > qg0) sacc[nt][0] = -1e30f;
                if (jg + 1 > qg0) sacc[nt][1] = -1e30f;
                if (jg     > qg1) sacc[nt][2] = -1e30f;
                if (jg + 1 > qg1) sacc[nt][3] = -1e30f;
            }
        }

        // ---- online softmax (base-2; per-row, quad shuffles) ----
        float t0 = -1e30f, t1 = -1e30f;
        #pragma unroll
        for (int nt = 0; nt < 8; nt++) {
            t0 = fmaxf(t0, fmaxf(sacc[nt][0], sacc[nt][1]));
            t1 = fmaxf(t1, fmaxf(sacc[nt][2], sacc[nt][3]));
        }
        t0 = fmaxf(t0, __shfl_xor_sync(0xffffffffu, t0, 1));
        t0 = fmaxf(t0, __shfl_xor_sync(0xffffffffu, t0, 2));
        t1 = fmaxf(t1, __shfl_xor_sync(0xffffffffu, t1, 1));
        t1 = fmaxf(t1, __shfl_xor_sync(0xffffffffu, t1, 2));
        float mn0 = fmaxf(m0r, t0), mn1 = fmaxf(m1r, t1);
        float al0 = exp2f(m0r - mn0), al1 = exp2f(m1r - mn1);
        m0r = mn0; m1r = mn1;
        #pragma unroll
        for (int nt = 0; nt < 8; nt++) {
            oacc[nt][0] *= al0; oacc[nt][1] *= al0;
            oacc[nt][2] *= al1; oacc[nt][3] *= al1;
        }

        // ---- P = exp2(S-m): build A-fragments in-register (hi & lo) ----
        unsigned ph[4][4], pl[4][4];
        float rs0 = 0.f, rs1 = 0.f;
        #pragma unroll
        for (int kt = 0; kt < 4; kt++) {
            float p00 = exp2f(sacc[2*kt    ][0] - mn0);
            float p01 = exp2f(sacc[2*kt    ][1] - mn0);
            float p02 = exp2f(sacc[2*kt    ][2] - mn1);
            float p03 = exp2f(sacc[2*kt    ][3] - mn1);
            float p10 = exp2f(sacc[2*kt + 1][0] - mn0);
            float p11 = exp2f(sacc[2*kt + 1][1] - mn0);
            float p12 = exp2f(sacc[2*kt + 1][2] - mn1);
            float p13 = exp2f(sacc[2*kt + 1][3] - mn1);
            rs0 += (p00 + p01) + (p10 + p11);
            rs1 += (p02 + p03) + (p12 + p13);
            ph[kt][0] = pack_hl(p00, p01, pl[kt][0]);
            ph[kt][1] = pack_hl(p02, p03, pl[kt][1]);
            ph[kt][2] = pack_hl(p10, p11, pl[kt][2]);
            ph[kt][3] = pack_hl(p12, p13, pl[kt][3]);
        }
        rs0 += __shfl_xor_sync(0xffffffffu, rs0, 1);
        rs0 += __shfl_xor_sync(0xffffffffu, rs0, 2);
        rs1 += __shfl_xor_sync(0xffffffffu, rs1, 1);
        rs1 += __shfl_xor_sync(0xffffffffu, rs1, 2);
        l0r = l0r * al0 + rs0;
        l1r = l1r * al1 + rs1;

        // ---- O += P @ V  (3-pass hi/lo, pass-outer per kt) ----
        #pragma unroll
        for (int kt = 0; kt < 4; kt++) {
            unsigned vbh[8][2], vbl[8][2];
            int vrow = 16 * kt + (lane & 15);
            #pragma unroll
            for (int nt = 0; nt < 8; nt++) {
                LDSM2T(vbh[nt], (unsigned)__cvta_generic_to_shared(&Vhs[vrow][8 * nt]));
                LDSM2T(vbl[nt], (unsigned)__cvta_generic_to_shared(&Vls[vrow][8 * nt]));
            }
            #pragma unroll
            for (int nt = 0; nt < 8; nt++) mma16816(oacc[nt], ph[kt], vbh[nt]);
            #pragma unroll
            for (int nt = 0; nt < 8; nt++) mma16816(oacc[nt], ph[kt], vbl[nt]);
            #pragma unroll
            for (int nt = 0; nt < 8; nt++) mma16816(oacc[nt], pl[kt], vbh[nt]);
        }
    }

    // ---- epilogue: O/l -> Ctx hi/lo bf16 [b, t, h*64+d] ----
    const float inv0 = 1.0f / l0r, inv1 = 1.0f / l1r;
    const int b = bh >> 4, h = bh & 15;
    size_t crow0 = ((size_t)(b * TT + qg0)) * CDIM + h * HD;
    size_t crow1 = ((size_t)(b * TT + qg1)) * CDIM + h * HD;
    #pragma unroll
    for (int nt = 0; nt < 8; nt++) {
        int d = 8 * nt + 2 * tig;
        unsigned lp;
        unsigned hp = pack_hl(oacc[nt][0] * inv0, oacc[nt][1] * inv0, lp);
        *(unsigned*)(g_Ch + crow0 + d) = hp;  *(unsigned*)(g_Cl + crow0 + d) = lp;
        hp = pack_hl(oacc[nt][2] * inv1, oacc[nt][3] * inv1, lp);
        *(unsigned*)(g_Ch + crow1 + d) = hp;  *(unsigned*)(g_Cl + crow1 + d) = lp;
    }
}

// ---------------------------------------------------------------------------
extern "C" void kernel_launch(void* const* d_in, const int* in_sizes, int n_in,
                              void* d_out, int out_size)
{
    const float* x      = (const float*)d_in[0];  // [4,2048,1024]
    const float* w_qkv  = (const float*)d_in[1];  // [3072,1024]
    const float* w_proj = (const float*)d_in[2];  // [1024,1024]
    float* out = (float*)d_out;                   // [4,2048,1024] fp32

    __nv_bfloat16 *xh, *xl, *wqh, *wql, *wph, *wpl;
    cudaGetSymbolAddress((void**)&xh,  g_Xh);  cudaGetSymbolAddress((void**)&xl,  g_Xl);
    cudaGetSymbolAddress((void**)&wqh, g_WQh); cudaGetSymbolAddress((void**)&wql, g_WQl);
    cudaGetSymbolAddress((void**)&wph, g_WPh); cudaGetSymbolAddress((void**)&wpl, g_WPl);

    const int GEMM_SMEM = 2 * GSTG * 2;   // 81920 B
    cudaFuncSetAttribute(gemm_mma_kernel<0>,
                         cudaFuncAttributeMaxDynamicSharedMemorySize, GEMM_SMEM);
    cudaFuncSetAttribute(gemm_mma_kernel<1>,
                         cudaFuncAttributeMaxDynamicSharedMemorySize, GEMM_SMEM);

    // 1) split inputs/weights to bf16 hi/lo
    split_kernel<<<(MROWS*CDIM/4 + 255)/256, 256>>>(x,      xh,  xl,  MROWS*CDIM/4);
    split_kernel<<<(NQKV*CDIM/4  + 255)/256, 256>>>(w_qkv,  wqh, wql, NQKV*CDIM/4);
    split_kernel<<<(CDIM*CDIM/4  + 255)/256, 256>>>(w_proj, wph, wpl, CDIM*CDIM/4);

    // 2) QKV projection -> Q/K/V hi/lo [bh,T,64]; Q pre-scaled by 0.125*log2e
    gemm_mma_kernel<0><<<dim3(NQKV/128, MROWS/128), 256, GEMM_SMEM>>>(nullptr);

    // 3) causal flash attention -> Ctx hi/lo
    attn_mma_kernel<<<dim3(TT/128, BB*NH), 256>>>();

    // 4) output projection -> fp32 out
    gemm_mma_kernel<1><<<dim3(CDIM/128, MROWS/128), 256, GEMM_SMEM>>>(out);
}